// round 1
// baseline (speedup 1.0000x reference)
#include <cuda_runtime.h>
#include <math.h>

// Problem constants
#define BATCH   2
#define SEQ     2048
#define DMODEL  1024
#define NHEAD   16
#define DK      64
#define MTOT    (BATCH*SEQ)           // 4096
#define OUT_OFF ((size_t)BATCH*SEQ*DMODEL)  // 4194304 floats, weights follow

// Scratch: projected Q/K/V and attention output (pre-W_o), 16 MB each.
__device__ float g_qp[MTOT*DMODEL];
__device__ float g_kp[MTOT*DMODEL];
__device__ float g_vp[MTOT*DMODEL];
__device__ float g_ao[MTOT*DMODEL];

// ---------------------------------------------------------------------------
// Generic C[M,N] = alpha * A[M,K] @ W[N,K]^T   (both row-major, "x @ W.T")
// Tile: BM=BN=128, BK=8, 256 threads, 8x8 per thread (split 4+4 fragments so
// smem compute loads are conflict-free float4s).
// Batched over blockIdx.z via (zo, zi) = (z/zdiv, z%zdiv) offset scheme.
// ---------------------------------------------------------------------------
__global__ __launch_bounds__(256) void gemm_xwt_kernel(
    const float* __restrict__ A, const float* __restrict__ W, float* __restrict__ C,
    int K, int lda, int ldw, int ldc, float alpha, int zdiv,
    long long sAo, long long sAi, long long sWo, long long sWi,
    long long sCo, long long sCi)
{
    const int z  = blockIdx.z;
    const int zo = z / zdiv, zi = z - zo * zdiv;
    A += (size_t)(zo * sAo + zi * sAi);
    W += (size_t)(zo * sWo + zi * sWi);
    C += (size_t)(zo * sCo + zi * sCi);

    __shared__ float As[8][132];
    __shared__ float Ws[8][132];

    const int tid = threadIdx.x;
    const int tx  = tid & 15;          // column group 0..15
    const int ty  = tid >> 4;          // row group 0..15
    const int rowBase = blockIdx.y * 128;
    const int colBase = blockIdx.x * 128;

    const int l_r = tid >> 1;          // 0..127
    const int l_c = (tid & 1) << 2;    // 0 or 4

    float acc[8][8];
    #pragma unroll
    for (int i = 0; i < 8; i++)
        #pragma unroll
        for (int j = 0; j < 8; j++) acc[i][j] = 0.f;

    const float* Aptr = A + (size_t)(rowBase + l_r) * lda + l_c;
    const float* Wptr = W + (size_t)(colBase + l_r) * ldw + l_c;

    for (int k0 = 0; k0 < K; k0 += 8) {
        float4 av = *(const float4*)(Aptr + k0);
        float4 wv = *(const float4*)(Wptr + k0);
        As[l_c+0][l_r] = av.x; As[l_c+1][l_r] = av.y;
        As[l_c+2][l_r] = av.z; As[l_c+3][l_r] = av.w;
        Ws[l_c+0][l_r] = wv.x; Ws[l_c+1][l_r] = wv.y;
        Ws[l_c+2][l_r] = wv.z; Ws[l_c+3][l_r] = wv.w;
        __syncthreads();
        #pragma unroll
        for (int kk = 0; kk < 8; kk++) {
            float4 a0 = *(const float4*)&As[kk][ty*4];
            float4 a1 = *(const float4*)&As[kk][64 + ty*4];
            float4 b0 = *(const float4*)&Ws[kk][tx*4];
            float4 b1 = *(const float4*)&Ws[kk][64 + tx*4];
            float a[8] = {a0.x,a0.y,a0.z,a0.w, a1.x,a1.y,a1.z,a1.w};
            float b[8] = {b0.x,b0.y,b0.z,b0.w, b1.x,b1.y,b1.z,b1.w};
            #pragma unroll
            for (int i = 0; i < 8; i++)
                #pragma unroll
                for (int j = 0; j < 8; j++)
                    acc[i][j] += a[i] * b[j];
        }
        __syncthreads();
    }

    #pragma unroll
    for (int ih = 0; ih < 2; ih++)
        #pragma unroll
        for (int i = 0; i < 4; i++) {
            int r = rowBase + ih*64 + ty*4 + i;
            int ai = ih*4 + i;
            float4 lo = make_float4(acc[ai][0]*alpha, acc[ai][1]*alpha,
                                    acc[ai][2]*alpha, acc[ai][3]*alpha);
            float4 hi = make_float4(acc[ai][4]*alpha, acc[ai][5]*alpha,
                                    acc[ai][6]*alpha, acc[ai][7]*alpha);
            *(float4*)&C[(size_t)r*ldc + colBase + tx*4]      = lo;
            *(float4*)&C[(size_t)r*ldc + colBase + 64 + tx*4] = hi;
        }
}

// ---------------------------------------------------------------------------
// Row softmax, in place: 65536 rows of length 2048. One block per row.
// ---------------------------------------------------------------------------
__global__ __launch_bounds__(256) void softmax_kernel(float* __restrict__ Wt)
{
    float* row = Wt + (size_t)blockIdx.x * SEQ;
    const int tid = threadIdx.x;
    __shared__ float red[8];

    float v[8];
    float m = -1e30f;
    #pragma unroll
    for (int i = 0; i < 8; i++) {
        v[i] = row[tid + 256*i];
        m = fmaxf(m, v[i]);
    }
    #pragma unroll
    for (int o = 16; o; o >>= 1) m = fmaxf(m, __shfl_xor_sync(0xFFFFFFFFu, m, o));
    if ((tid & 31) == 0) red[tid >> 5] = m;
    __syncthreads();
    m = red[0];
    #pragma unroll
    for (int i = 1; i < 8; i++) m = fmaxf(m, red[i]);
    __syncthreads();

    float e[8];
    float s = 0.f;
    #pragma unroll
    for (int i = 0; i < 8; i++) { e[i] = __expf(v[i] - m); s += e[i]; }
    #pragma unroll
    for (int o = 16; o; o >>= 1) s += __shfl_xor_sync(0xFFFFFFFFu, s, o);
    if ((tid & 31) == 0) red[tid >> 5] = s;
    __syncthreads();
    s = red[0];
    #pragma unroll
    for (int i = 1; i < 8; i++) s += red[i];
    float inv = 1.f / s;

    #pragma unroll
    for (int i = 0; i < 8; i++) row[tid + 256*i] = e[i] * inv;
}

// ---------------------------------------------------------------------------
// attn_out[b, q, h*64+d] = sum_k P[bh, q, k] * Vp[b, k, h*64+d]
// Per (b,h) GEMM: [2048,2048] @ [2048,64]. BM=128, BN=64, BK=16,
// 256 threads, 8x4 per thread.
// ---------------------------------------------------------------------------
__global__ __launch_bounds__(256) void pv_kernel(
    const float* __restrict__ P, const float* __restrict__ V, float* __restrict__ C)
{
    const int z = blockIdx.z;          // bh
    const int b = z >> 4, h = z & 15;
    P += (size_t)z * SEQ * SEQ;
    V += (size_t)b * SEQ * DMODEL + h * DK;
    C += (size_t)b * SEQ * DMODEL + h * DK;

    __shared__ float Ps[16][132];
    __shared__ float Vs[16][68];

    const int tid = threadIdx.x;
    const int tx  = tid & 15;          // col group (0..15) -> d = tx*4..+4
    const int ty  = tid >> 4;          // row group
    const int rowBase = blockIdx.y * 128;

    float acc[8][4];
    #pragma unroll
    for (int i = 0; i < 8; i++)
        #pragma unroll
        for (int j = 0; j < 4; j++) acc[i][j] = 0.f;

    for (int k0 = 0; k0 < SEQ; k0 += 16) {
        #pragma unroll
        for (int it = 0; it < 2; it++) {
            int r = (tid >> 2) + it*64;
            int c = (tid & 3) << 2;
            float4 pv = *(const float4*)&P[(size_t)(rowBase + r)*SEQ + k0 + c];
            Ps[c+0][r]=pv.x; Ps[c+1][r]=pv.y; Ps[c+2][r]=pv.z; Ps[c+3][r]=pv.w;
        }
        {
            int kk = tid >> 4;
            int n0 = (tid & 15) << 2;
            float4 vv = *(const float4*)&V[(size_t)(k0 + kk)*DMODEL + n0];
            *(float4*)&Vs[kk][n0] = vv;
        }
        __syncthreads();
        #pragma unroll
        for (int kk = 0; kk < 16; kk++) {
            float4 a0 = *(const float4*)&Ps[kk][ty*4];
            float4 a1 = *(const float4*)&Ps[kk][64 + ty*4];
            float4 bb = *(const float4*)&Vs[kk][tx*4];
            float a[8] = {a0.x,a0.y,a0.z,a0.w, a1.x,a1.y,a1.z,a1.w};
            float bv[4] = {bb.x, bb.y, bb.z, bb.w};
            #pragma unroll
            for (int i = 0; i < 8; i++)
                #pragma unroll
                for (int j = 0; j < 4; j++)
                    acc[i][j] += a[i] * bv[j];
        }
        __syncthreads();
    }

    #pragma unroll
    for (int ih = 0; ih < 2; ih++)
        #pragma unroll
        for (int i = 0; i < 4; i++) {
            int r = rowBase + ih*64 + ty*4 + i;
            int ai = ih*4 + i;
            *(float4*)&C[(size_t)r*DMODEL + tx*4] =
                make_float4(acc[ai][0], acc[ai][1], acc[ai][2], acc[ai][3]);
        }
}

// ---------------------------------------------------------------------------
extern "C" void kernel_launch(void* const* d_in, const int* in_sizes, int n_in,
                              void* d_out, int out_size)
{
    const float* q  = (const float*)d_in[0];
    const float* k  = (const float*)d_in[1];
    const float* v  = (const float*)d_in[2];
    const float* Wq = (const float*)d_in[3];
    const float* Wk = (const float*)d_in[4];
    const float* Wv = (const float*)d_in[5];
    const float* Wo = (const float*)d_in[6];
    float* out = (float*)d_out;
    float* wts = out + OUT_OFF;   // attn_weights region [B,H,S,S]

    float *qp, *kp, *vp, *ao;
    cudaGetSymbolAddress((void**)&qp, g_qp);
    cudaGetSymbolAddress((void**)&kp, g_kp);
    cudaGetSymbolAddress((void**)&vp, g_vp);
    cudaGetSymbolAddress((void**)&ao, g_ao);

    const dim3 thr(256);
    const float inv_sqrt_dk = 0.125f;   // 1/sqrt(64)

    // Projections: [4096,1024] @ [1024,1024]^T
    gemm_xwt_kernel<<<dim3(8,32,1), thr>>>(q, Wq, qp, DMODEL, DMODEL, DMODEL, DMODEL,
                                           1.f, 1, 0,0,0,0,0,0);
    gemm_xwt_kernel<<<dim3(8,32,1), thr>>>(k, Wk, kp, DMODEL, DMODEL, DMODEL, DMODEL,
                                           1.f, 1, 0,0,0,0,0,0);
    gemm_xwt_kernel<<<dim3(8,32,1), thr>>>(v, Wv, vp, DMODEL, DMODEL, DMODEL, DMODEL,
                                           1.f, 1, 0,0,0,0,0,0);

    // Scores: per (b,h): Qh[2048,64] @ Kh[2048,64]^T * 0.125 -> wts[bh]
    gemm_xwt_kernel<<<dim3(16,16,32), thr>>>(
        qp, kp, wts, DK, DMODEL, DMODEL, SEQ, inv_sqrt_dk,
        NHEAD,
        (long long)SEQ*DMODEL, (long long)DK,      // A: b-stride, h-stride
        (long long)SEQ*DMODEL, (long long)DK,      // W: b-stride, h-stride
        (long long)NHEAD*SEQ*SEQ, (long long)SEQ*SEQ); // C: b-stride, h-stride

    // Softmax in place over 65536 rows of 2048
    softmax_kernel<<<BATCH*NHEAD*SEQ, 256>>>(wts);

    // P @ V -> attn_out (interleaved back to [B,S,D])
    pv_kernel<<<dim3(1,16,32), thr>>>(wts, vp, ao);

    // Output projection: [4096,1024] @ Wo^T -> out
    gemm_xwt_kernel<<<dim3(8,32,1), thr>>>(ao, Wo, out, DMODEL, DMODEL, DMODEL, DMODEL,
                                           1.f, 1, 0,0,0,0,0,0);
}

// round 3
// speedup vs baseline: 1.9697x; 1.9697x over previous
#include <cuda_runtime.h>
#include <stdint.h>
#include <math.h>

#define BATCH   2
#define SEQ     2048
#define DMODEL  1024
#define NHEAD   16
#define DK      64
#define MTOT    (BATCH*SEQ)
#define OUT_OFF ((size_t)MTOT*DMODEL)

// Scratch: projected Q/K/V and attention output (pre-W_o)
__device__ float g_qp[MTOT*DMODEL];
__device__ float g_kp[MTOT*DMODEL];
__device__ float g_vp[MTOT*DMODEL];
__device__ float g_ao[MTOT*DMODEL];

// ---------------------------------------------------------------------------
__device__ __forceinline__ uint32_t f2tf32(float x) {
    uint32_t u;
    asm("cvt.rna.tf32.f32 %0, %1;" : "=r"(u) : "f"(x));
    return u;
}

__device__ __forceinline__ float4 cvt4(float4 v) {
    float4 r;
    r.x = __uint_as_float(f2tf32(v.x));
    r.y = __uint_as_float(f2tf32(v.y));
    r.z = __uint_as_float(f2tf32(v.z));
    r.w = __uint_as_float(f2tf32(v.w));
    return r;
}

__device__ __forceinline__ void mma_tf32(float* d, const uint32_t* a, const uint32_t* b) {
    asm volatile(
        "mma.sync.aligned.m16n8k8.row.col.f32.tf32.tf32.f32 "
        "{%0,%1,%2,%3}, {%4,%5,%6,%7}, {%8,%9}, {%0,%1,%2,%3};"
        : "+f"(d[0]), "+f"(d[1]), "+f"(d[2]), "+f"(d[3])
        : "r"(a[0]), "r"(a[1]), "r"(a[2]), "r"(a[3]), "r"(b[0]), "r"(b[1]));
}

// ---------------------------------------------------------------------------
// NT: C[M,N] = alpha * A[M,K] @ B[N,K]^T (both row-major). BM=BN=128, BK=16.
// 256 threads = 8 warps in 2x4 grid; warp tile 64x32 (4 m16 x 4 n8).
// Batched over blockIdx.z via (zo,zi) offsets.
// ---------------------------------------------------------------------------
__global__ __launch_bounds__(256, 2) void gemm_tf32_nt(
    const float* __restrict__ A, const float* __restrict__ B, float* __restrict__ C,
    int K, int lda, int ldb, int ldc, float alpha, int zdiv,
    long long sAo, long long sAi, long long sBo, long long sBi,
    long long sCo, long long sCi)
{
    const int z  = blockIdx.z;
    const int zo = z / zdiv, zi = z - zo * zdiv;
    A += zo * sAo + zi * sAi;
    B += zo * sBo + zi * sBi;
    C += zo * sCo + zi * sCi;

    __shared__ float As[2][128][20];   // m-major, stride 20 -> conflict-free frags
    __shared__ float Bs[2][128][20];   // n-major

    const int tid  = threadIdx.x;
    const int lane = tid & 31;
    const int warp = tid >> 5;
    const int wm   = warp >> 2;        // 0..1 -> m offset wm*64
    const int wn   = warp & 3;         // 0..3 -> n offset wn*32
    const int q    = lane & 3;
    const int lr   = lane >> 2;        // 0..7

    const int mBase = blockIdx.y * 128;
    const int nBase = blockIdx.x * 128;

    const int r0 = tid >> 2;           // 0..63
    const int c4 = (tid & 3) << 2;     // 0,4,8,12

    float acc[4][4][4];
    #pragma unroll
    for (int i = 0; i < 4; i++)
        #pragma unroll
        for (int j = 0; j < 4; j++)
            #pragma unroll
            for (int t = 0; t < 4; t++) acc[i][j][t] = 0.f;

    const float* Ag = A + (size_t)mBase * lda;
    const float* Bg = B + (size_t)nBase * ldb;

    // prefetch chunk 0
    float4 pa0 = *(const float4*)(Ag + (size_t)r0 * lda + c4);
    float4 pa1 = *(const float4*)(Ag + (size_t)(r0 + 64) * lda + c4);
    float4 pb0 = *(const float4*)(Bg + (size_t)r0 * ldb + c4);
    float4 pb1 = *(const float4*)(Bg + (size_t)(r0 + 64) * ldb + c4);
    *(float4*)&As[0][r0][c4]      = cvt4(pa0);
    *(float4*)&As[0][r0 + 64][c4] = cvt4(pa1);
    *(float4*)&Bs[0][r0][c4]      = cvt4(pb0);
    *(float4*)&Bs[0][r0 + 64][c4] = cvt4(pb1);
    __syncthreads();

    const int nc = K >> 4;
    for (int ch = 0; ch < nc; ch++) {
        const int cur  = ch & 1;
        const bool more = (ch + 1 < nc);
        if (more) {
            const int k0 = (ch + 1) << 4;
            pa0 = *(const float4*)(Ag + (size_t)r0 * lda + k0 + c4);
            pa1 = *(const float4*)(Ag + (size_t)(r0 + 64) * lda + k0 + c4);
            pb0 = *(const float4*)(Bg + (size_t)r0 * ldb + k0 + c4);
            pb1 = *(const float4*)(Bg + (size_t)(r0 + 64) * ldb + k0 + c4);
        }

        #pragma unroll
        for (int ks = 0; ks < 2; ks++) {
            const int kb = ks * 8 + q;
            uint32_t af[4][4], bf[4][2];
            #pragma unroll
            for (int mi = 0; mi < 4; mi++) {
                const int m0 = wm * 64 + mi * 16 + lr;
                af[mi][0] = __float_as_uint(As[cur][m0][kb]);
                af[mi][1] = __float_as_uint(As[cur][m0 + 8][kb]);
                af[mi][2] = __float_as_uint(As[cur][m0][kb + 4]);
                af[mi][3] = __float_as_uint(As[cur][m0 + 8][kb + 4]);
            }
            #pragma unroll
            for (int ni = 0; ni < 4; ni++) {
                const int n0 = wn * 32 + ni * 8 + lr;
                bf[ni][0] = __float_as_uint(Bs[cur][n0][kb]);
                bf[ni][1] = __float_as_uint(Bs[cur][n0][kb + 4]);
            }
            #pragma unroll
            for (int mi = 0; mi < 4; mi++)
                #pragma unroll
                for (int ni = 0; ni < 4; ni++)
                    mma_tf32(acc[mi][ni], af[mi], bf[ni]);
        }
        __syncthreads();
        if (more) {
            const int nxt = cur ^ 1;
            *(float4*)&As[nxt][r0][c4]      = cvt4(pa0);
            *(float4*)&As[nxt][r0 + 64][c4] = cvt4(pa1);
            *(float4*)&Bs[nxt][r0][c4]      = cvt4(pb0);
            *(float4*)&Bs[nxt][r0 + 64][c4] = cvt4(pb1);
            __syncthreads();
        }
    }

    #pragma unroll
    for (int mi = 0; mi < 4; mi++) {
        const int row0 = mBase + wm * 64 + mi * 16 + lr;
        #pragma unroll
        for (int ni = 0; ni < 4; ni++) {
            const int col = nBase + wn * 32 + ni * 8 + q * 2;
            *(float2*)&C[(size_t)row0 * ldc + col] =
                make_float2(acc[mi][ni][0] * alpha, acc[mi][ni][1] * alpha);
            *(float2*)&C[(size_t)(row0 + 8) * ldc + col] =
                make_float2(acc[mi][ni][2] * alpha, acc[mi][ni][3] * alpha);
        }
    }
}

// ---------------------------------------------------------------------------
// NN: C[M,64] = A[M,K] @ B[K,64]  (B row-major over K). BM=128, BN=64, BK=16.
// 8 warps in 4x2 grid; warp tile 32x32 (2 m16 x 4 n8). Used for P @ V.
// ---------------------------------------------------------------------------
__global__ __launch_bounds__(256, 2) void gemm_tf32_nn64(
    const float* __restrict__ A, const float* __restrict__ B, float* __restrict__ C,
    int K, int lda, int ldb, int ldc)
{
    const int z = blockIdx.z;          // bh
    const int b = z >> 4, h = z & 15;
    A += (size_t)z * SEQ * SEQ;
    B += (size_t)b * SEQ * DMODEL + h * DK;
    C += (size_t)b * SEQ * DMODEL + h * DK;

    __shared__ float As[2][128][20];
    __shared__ float Bs[2][16][72];    // k-major, stride 72 -> conflict-free frags

    const int tid  = threadIdx.x;
    const int lane = tid & 31;
    const int warp = tid >> 5;
    const int wm   = warp >> 1;        // 0..3 -> m offset wm*32
    const int wn   = warp & 1;         // 0..1 -> n offset wn*32
    const int q    = lane & 3;
    const int lr   = lane >> 2;

    const int mBase = blockIdx.y * 128;

    const int r0 = tid >> 2;           // A loader rows
    const int c4 = (tid & 3) << 2;
    const int kr = tid >> 4;           // B loader: k row 0..15
    const int n4 = (tid & 15) << 2;    // B loader: n 0..60

    float acc[2][4][4];
    #pragma unroll
    for (int i = 0; i < 2; i++)
        #pragma unroll
        for (int j = 0; j < 4; j++)
            #pragma unroll
            for (int t = 0; t < 4; t++) acc[i][j][t] = 0.f;

    const float* Ag = A + (size_t)mBase * lda;

    float4 pa0 = *(const float4*)(Ag + (size_t)r0 * lda + c4);
    float4 pa1 = *(const float4*)(Ag + (size_t)(r0 + 64) * lda + c4);
    float4 pb  = *(const float4*)(B + (size_t)kr * ldb + n4);
    *(float4*)&As[0][r0][c4]      = cvt4(pa0);
    *(float4*)&As[0][r0 + 64][c4] = cvt4(pa1);
    *(float4*)&Bs[0][kr][n4]      = cvt4(pb);
    __syncthreads();

    const int nc = K >> 4;
    for (int ch = 0; ch < nc; ch++) {
        const int cur  = ch & 1;
        const bool more = (ch + 1 < nc);
        if (more) {
            const int k0 = (ch + 1) << 4;
            pa0 = *(const float4*)(Ag + (size_t)r0 * lda + k0 + c4);
            pa1 = *(const float4*)(Ag + (size_t)(r0 + 64) * lda + k0 + c4);
            pb  = *(const float4*)(B + (size_t)(k0 + kr) * ldb + n4);
        }

        #pragma unroll
        for (int ks = 0; ks < 2; ks++) {
            const int kb = ks * 8 + q;
            uint32_t af[2][4], bf[4][2];
            #pragma unroll
            for (int mi = 0; mi < 2; mi++) {
                const int m0 = wm * 32 + mi * 16 + lr;
                af[mi][0] = __float_as_uint(As[cur][m0][kb]);
                af[mi][1] = __float_as_uint(As[cur][m0 + 8][kb]);
                af[mi][2] = __float_as_uint(As[cur][m0][kb + 4]);
                af[mi][3] = __float_as_uint(As[cur][m0 + 8][kb + 4]);
            }
            #pragma unroll
            for (int ni = 0; ni < 4; ni++) {
                const int n0 = wn * 32 + ni * 8 + lr;
                bf[ni][0] = __float_as_uint(Bs[cur][kb][n0]);
                bf[ni][1] = __float_as_uint(Bs[cur][kb + 4][n0]);
            }
            #pragma unroll
            for (int mi = 0; mi < 2; mi++)
                #pragma unroll
                for (int ni = 0; ni < 4; ni++)
                    mma_tf32(acc[mi][ni], af[mi], bf[ni]);
        }
        __syncthreads();
        if (more) {
            const int nxt = cur ^ 1;
            *(float4*)&As[nxt][r0][c4]      = cvt4(pa0);
            *(float4*)&As[nxt][r0 + 64][c4] = cvt4(pa1);
            *(float4*)&Bs[nxt][kr][n4]      = cvt4(pb);
            __syncthreads();
        }
    }

    #pragma unroll
    for (int mi = 0; mi < 2; mi++) {
        const int row0 = mBase + wm * 32 + mi * 16 + lr;
        #pragma unroll
        for (int ni = 0; ni < 4; ni++) {
            const int col = wn * 32 + ni * 8 + q * 2;
            *(float2*)&C[(size_t)row0 * ldc + col] =
                make_float2(acc[mi][ni][0], acc[mi][ni][1]);
            *(float2*)&C[(size_t)(row0 + 8) * ldc + col] =
                make_float2(acc[mi][ni][2], acc[mi][ni][3]);
        }
    }
}

// ---------------------------------------------------------------------------
// Row softmax, in place: 65536 rows of length 2048.
// ---------------------------------------------------------------------------
__global__ __launch_bounds__(256) void softmax_kernel(float* __restrict__ Wt)
{
    float* row = Wt + (size_t)blockIdx.x * SEQ;
    const int tid = threadIdx.x;
    __shared__ float red[8];

    float v[8];
    float m = -1e30f;
    #pragma unroll
    for (int i = 0; i < 8; i++) {
        v[i] = row[tid + 256 * i];
        m = fmaxf(m, v[i]);
    }
    #pragma unroll
    for (int o = 16; o; o >>= 1) m = fmaxf(m, __shfl_xor_sync(0xFFFFFFFFu, m, o));
    if ((tid & 31) == 0) red[tid >> 5] = m;
    __syncthreads();
    m = red[0];
    #pragma unroll
    for (int i = 1; i < 8; i++) m = fmaxf(m, red[i]);
    __syncthreads();

    float e[8];
    float s = 0.f;
    #pragma unroll
    for (int i = 0; i < 8; i++) { e[i] = __expf(v[i] - m); s += e[i]; }
    #pragma unroll
    for (int o = 16; o; o >>= 1) s += __shfl_xor_sync(0xFFFFFFFFu, s, o);
    if ((tid & 31) == 0) red[tid >> 5] = s;
    __syncthreads();
    s = red[0];
    #pragma unroll
    for (int i = 1; i < 8; i++) s += red[i];
    const float inv = 1.f / s;

    #pragma unroll
    for (int i = 0; i < 8; i++) row[tid + 256 * i] = e[i] * inv;
}

// ---------------------------------------------------------------------------
extern "C" void kernel_launch(void* const* d_in, const int* in_sizes, int n_in,
                              void* d_out, int out_size)
{
    const float* q  = (const float*)d_in[0];
    const float* k  = (const float*)d_in[1];
    const float* v  = (const float*)d_in[2];
    const float* Wq = (const float*)d_in[3];
    const float* Wk = (const float*)d_in[4];
    const float* Wv = (const float*)d_in[5];
    const float* Wo = (const float*)d_in[6];
    float* out = (float*)d_out;
    float* wts = out + OUT_OFF;

    float *qp, *kp, *vp, *ao;
    cudaGetSymbolAddress((void**)&qp, g_qp);
    cudaGetSymbolAddress((void**)&kp, g_kp);
    cudaGetSymbolAddress((void**)&vp, g_vp);
    cudaGetSymbolAddress((void**)&ao, g_ao);

    const dim3 thr(256);
    const float inv_sqrt_dk = 0.125f;

    // Projections: [4096,1024] @ [1024,1024]^T
    gemm_tf32_nt<<<dim3(8, 32, 1), thr>>>(q, Wq, qp, DMODEL, DMODEL, DMODEL, DMODEL,
                                          1.f, 1, 0, 0, 0, 0, 0, 0);
    gemm_tf32_nt<<<dim3(8, 32, 1), thr>>>(k, Wk, kp, DMODEL, DMODEL, DMODEL, DMODEL,
                                          1.f, 1, 0, 0, 0, 0, 0, 0);
    gemm_tf32_nt<<<dim3(8, 32, 1), thr>>>(v, Wv, vp, DMODEL, DMODEL, DMODEL, DMODEL,
                                          1.f, 1, 0, 0, 0, 0, 0, 0);

    // Scores: per (b,h): Qh[2048,64] @ Kh[2048,64]^T * 0.125 -> wts[bh]
    gemm_tf32_nt<<<dim3(16, 16, 32), thr>>>(
        qp, kp, wts, DK, DMODEL, DMODEL, SEQ, inv_sqrt_dk, NHEAD,
        (long long)SEQ * DMODEL, (long long)DK,
        (long long)SEQ * DMODEL, (long long)DK,
        (long long)NHEAD * SEQ * SEQ, (long long)SEQ * SEQ);

    // Softmax in place
    softmax_kernel<<<BATCH * NHEAD * SEQ, 256>>>(wts);

    // P @ V -> attn_out
    gemm_tf32_nn64<<<dim3(1, 16, 32), thr>>>(wts, vp, ao, SEQ, SEQ, DMODEL, DMODEL);

    // Output projection
    gemm_tf32_nt<<<dim3(8, 32, 1), thr>>>(ao, Wo, out, DMODEL, DMODEL, DMODEL, DMODEL,
                                          1.f, 1, 0, 0, 0, 0, 0, 0);
}